// round 8
// baseline (speedup 1.0000x reference)
#include <cuda_runtime.h>
#include <cuda_fp16.h>
#include <cuda_bf16.h>
#include <cstdint>

// Sliding-window block-causal attention, FA2-style with mma.sync (HMMA).
// B=4 H=16 S=4096 D=64, BLK=16, W=32 -> window start = (q & ~15) - 496, causal.
// Inputs are float32 (verified; 16-bit fallback retained). R8: K/V prefetched
// one tile ahead via LDG.128 into REGISTERS (no smem staging round-trip),
// converted to fp16 smem at tile boundary. smem traffic/tile: 144KB -> 80KB.

constexpr int S_ = 4096;
constexpr int D_ = 64;
constexpr int MT = 64;          // query rows per CTA
constexpr int NT = 64;          // key rows per KV tile
constexpr int STRIDE = 72;      // smem row stride in halves (64 + 8 pad)
constexpr float SL2E = 0.125f * 1.4426950408889634f; // scale * log2(e)

__device__ __forceinline__ uint32_t smem_u32(const void* p) {
    return (uint32_t)__cvta_generic_to_shared(p);
}

__device__ __forceinline__ float ex2(float x) {
    float y;
    asm("ex2.approx.ftz.f32 %0, %1;" : "=f"(y) : "f"(x));
    return y;
}

__device__ __forceinline__ void mma16816(float c[4], uint32_t a0, uint32_t a1,
                                         uint32_t a2, uint32_t a3,
                                         uint32_t b0, uint32_t b1) {
    asm volatile(
        "mma.sync.aligned.m16n8k16.row.col.f32.f16.f16.f32 "
        "{%0,%1,%2,%3},{%4,%5,%6,%7},{%8,%9},{%0,%1,%2,%3};"
        : "+f"(c[0]), "+f"(c[1]), "+f"(c[2]), "+f"(c[3])
        : "r"(a0), "r"(a1), "r"(a2), "r"(a3), "r"(b0), "r"(b1));
}

// 16-bit fallback: load 64x64 tile to padded fp16 smem with scale
__device__ __forceinline__ void load_tile16(const uint16_t* __restrict__ src,
                                            __half* dst, int tid, int mode,
                                            float scale) {
#pragma unroll
    for (int i = 0; i < 4; i++) {
        int idx = tid + i * 128;
        int r = idx >> 3, c = (idx & 7) * 8;
        uint4 v = *(const uint4*)&src[r * D_ + c];
        uint32_t* w = (uint32_t*)&v;
#pragma unroll
        for (int e = 0; e < 4; e++) {
            float2 f = (mode == 2) ? __bfloat1622float2(*(__nv_bfloat162*)&w[e])
                                   : __half22float2(*(__half2*)&w[e]);
            __half2 h = __floats2half2_rn(f.x * scale, f.y * scale);
            w[e] = *(uint32_t*)&h;
        }
        *(uint4*)&dst[r * STRIDE + c] = v;
    }
}

__global__ __launch_bounds__(128, 3)
void swattn_kernel(const void* __restrict__ Q, const void* __restrict__ K,
                   const void* __restrict__ V, void* __restrict__ O) {
    __shared__ __half sQ[MT * STRIDE];
    __shared__ __half sK[NT * STRIDE];
    __shared__ __half sV[NT * STRIDE];
    __shared__ int s_mode;

    const int tid  = threadIdx.x;
    const int lane = tid & 31;
    const int warp = tid >> 5;
    const int q0   = blockIdx.x * MT;
    const size_t base = (size_t)blockIdx.y * ((size_t)S_ * D_);

    // ---- dtype probe (128 words of Q): bf16-exponent field of halves ----
    if (tid == 0) {
        const uint32_t* w = (const uint32_t*)Q;
        int evenCnt = 0, oddCnt = 0;
        for (int i = 0; i < 128; i++) {
            uint32_t x = w[i];
            uint32_t elo = (x >> 7) & 0xff;
            uint32_t ehi = (x >> 23) & 0xff;
            evenCnt += (elo >= 117 && elo <= 132) ? 1 : 0;
            oddCnt  += (ehi >= 117 && ehi <= 132) ? 1 : 0;
        }
        s_mode = (oddCnt < 90) ? 1 : ((evenCnt > 102) ? 2 : 0);
    }
    __syncthreads();
    const int mode = s_mode;

    int kt_lo = q0 - 512;
    if (kt_lo < 0) kt_lo = 0;

    // Each thread owns 32 consecutive floats of one K row and one V row:
    // row = tid>>1, col0 = (tid&1)*32  -> 8 float4 LDGs each for K and V.
    const int prow = tid >> 1;
    const int pcol = (tid & 1) * 32;
    float4 kreg[8], vreg[8];

    // ---- prologue: prefetch first KV tile into registers (fp32 path) ----
    if (mode == 0) {
        const float* Ks = (const float*)K + base + (size_t)kt_lo * D_ + prow * D_ + pcol;
        const float* Vs = (const float*)V + base + (size_t)kt_lo * D_ + prow * D_ + pcol;
#pragma unroll
        for (int j = 0; j < 8; j++) {
            kreg[j] = *(const float4*)&Ks[j * 4];
            vreg[j] = *(const float4*)&Vs[j * 4];
        }
    }

    // ---- load Q tile (scaled by SL2E) ----
    if (mode == 0) {
        const float* Qs = (const float*)Q + base + (size_t)q0 * D_;
#pragma unroll
        for (int i = 0; i < 8; i++) {
            int idx = tid + i * 128;
            int r = idx >> 4, c = (idx & 15) * 4;
            float4 v = *(const float4*)&Qs[r * D_ + c];
            *(__half2*)&sQ[r * STRIDE + c]     = __floats2half2_rn(v.x * SL2E, v.y * SL2E);
            *(__half2*)&sQ[r * STRIDE + c + 2] = __floats2half2_rn(v.z * SL2E, v.w * SL2E);
        }
    } else {
        load_tile16((const uint16_t*)Q + base + (size_t)q0 * D_, sQ, tid, mode, SL2E);
    }
    __syncthreads();

    // ---- Q fragments: 4 k-steps of m16k16 per warp ----
    uint32_t qf[4][4];
    {
        int row  = warp * 16 + (lane & 15);
        int colb = (lane >> 4) * 8;
#pragma unroll
        for (int ks = 0; ks < 4; ks++) {
            uint32_t a = smem_u32(&sQ[row * STRIDE + ks * 16 + colb]);
            asm volatile("ldmatrix.sync.aligned.m8n8.x4.shared.b16 {%0,%1,%2,%3},[%4];"
                         : "=r"(qf[ks][0]), "=r"(qf[ks][1]),
                           "=r"(qf[ks][2]), "=r"(qf[ks][3])
                         : "r"(a));
        }
    }

    float oacc[8][4];
#pragma unroll
    for (int j = 0; j < 8; j++) {
        oacc[j][0] = 0.f; oacc[j][1] = 0.f; oacc[j][2] = 0.f; oacc[j][3] = 0.f;
    }
    float l0 = 0.f, l1 = 0.f;

    const int g    = lane >> 2;
    const int tq   = lane & 3;
    const int qr0  = q0 + warp * 16 + g;
    const int qr1  = qr0 + 8;
    const int low0 = (qr0 & ~15) - 496;
    const int low1 = (qr1 & ~15) - 496;

    for (int kt = kt_lo; kt <= q0; kt += NT) {
        if (mode == 0) {
            __syncthreads();   // previous tile's LDSM reads complete
            // convert prefetched regs -> fp16 smem (4+4 STS.128 per thread)
#pragma unroll
            for (int i = 0; i < 4; i++) {
                __half2 ka = __floats2half2_rn(kreg[2*i].x, kreg[2*i].y);
                __half2 kb = __floats2half2_rn(kreg[2*i].z, kreg[2*i].w);
                __half2 kc = __floats2half2_rn(kreg[2*i+1].x, kreg[2*i+1].y);
                __half2 kd = __floats2half2_rn(kreg[2*i+1].z, kreg[2*i+1].w);
                *(uint4*)&sK[prow * STRIDE + pcol + i * 8] =
                    make_uint4(*(uint32_t*)&ka, *(uint32_t*)&kb,
                               *(uint32_t*)&kc, *(uint32_t*)&kd);
                __half2 va = __floats2half2_rn(vreg[2*i].x, vreg[2*i].y);
                __half2 vb = __floats2half2_rn(vreg[2*i].z, vreg[2*i].w);
                __half2 vc = __floats2half2_rn(vreg[2*i+1].x, vreg[2*i+1].y);
                __half2 vd = __floats2half2_rn(vreg[2*i+1].z, vreg[2*i+1].w);
                *(uint4*)&sV[prow * STRIDE + pcol + i * 8] =
                    make_uint4(*(uint32_t*)&va, *(uint32_t*)&vb,
                               *(uint32_t*)&vc, *(uint32_t*)&vd);
            }
            __syncthreads();
            // prefetch next tile into registers (overlaps with compute below)
            int ktn = kt + NT;
            if (ktn <= q0) {
                const float* Ks = (const float*)K + base + (size_t)ktn * D_ + prow * D_ + pcol;
                const float* Vs = (const float*)V + base + (size_t)ktn * D_ + prow * D_ + pcol;
#pragma unroll
                for (int j = 0; j < 8; j++) {
                    kreg[j] = *(const float4*)&Ks[j * 4];
                    vreg[j] = *(const float4*)&Vs[j * 4];
                }
            }
        } else {
            __syncthreads();
            load_tile16((const uint16_t*)K + base + (size_t)kt * D_, sK, tid, mode, 1.f);
            load_tile16((const uint16_t*)V + base + (size_t)kt * D_, sV, tid, mode, 1.f);
            __syncthreads();
        }

        const bool full = (kt >= q0 - 448) && (kt + NT <= q0);

        // ---- two 32-key chunks: QK -> softmax -> PV ----
#pragma unroll
        for (int h = 0; h < 2; h++) {
            float sacc[4][4];
#pragma unroll
            for (int j = 0; j < 4; j++) {
                sacc[j][0] = 0.f; sacc[j][1] = 0.f; sacc[j][2] = 0.f; sacc[j][3] = 0.f;
            }
#pragma unroll
            for (int ks = 0; ks < 4; ks++) {
#pragma unroll
                for (int jp = 0; jp < 2; jp++) {
                    int r = h * 32 + jp * 16 + ((lane >> 4) << 3) + (lane & 7);
                    int c = ks * 16 + ((lane >> 3) & 1) * 8;
                    uint32_t a = smem_u32(&sK[r * STRIDE + c]);
                    uint32_t b0, b1, b2, b3;
                    asm volatile("ldmatrix.sync.aligned.m8n8.x4.shared.b16 {%0,%1,%2,%3},[%4];"
                                 : "=r"(b0), "=r"(b1), "=r"(b2), "=r"(b3) : "r"(a));
                    mma16816(sacc[2 * jp],     qf[ks][0], qf[ks][1], qf[ks][2], qf[ks][3], b0, b1);
                    mma16816(sacc[2 * jp + 1], qf[ks][0], qf[ks][1], qf[ks][2], qf[ks][3], b2, b3);
                }
            }

            uint32_t ph[4][2];
            float rs0 = 0.f, rs1 = 0.f;
#pragma unroll
            for (int j = 0; j < 4; j++) {
                float p0 = ex2(sacc[j][0]);
                float p1 = ex2(sacc[j][1]);
                float p2 = ex2(sacc[j][2]);
                float p3 = ex2(sacc[j][3]);
                if (!full) {
                    int k0 = kt + h * 32 + j * 8 + tq * 2;
                    int k1 = k0 + 1;
                    if (!(k0 <= qr0 && k0 >= low0)) p0 = 0.f;
                    if (!(k1 <= qr0 && k1 >= low0)) p1 = 0.f;
                    if (!(k0 <= qr1 && k0 >= low1)) p2 = 0.f;
                    if (!(k1 <= qr1 && k1 >= low1)) p3 = 0.f;
                }
                rs0 += p0 + p1;
                rs1 += p2 + p3;
                __half2 h01 = __floats2half2_rn(p0, p1);
                __half2 h23 = __floats2half2_rn(p2, p3);
                ph[j][0] = *(uint32_t*)&h01;
                ph[j][1] = *(uint32_t*)&h23;
            }
            l0 += rs0;
            l1 += rs1;

            // PV for this 32-key chunk
#pragma unroll
            for (int kkl = 0; kkl < 2; kkl++) {
                uint32_t a0 = ph[2 * kkl][0], a1 = ph[2 * kkl][1];
                uint32_t a2 = ph[2 * kkl + 1][0], a3 = ph[2 * kkl + 1][1];
#pragma unroll
                for (int jp = 0; jp < 4; jp++) {
                    int r = h * 32 + kkl * 16 + (lane & 15);
                    int c = jp * 16 + ((lane >> 4) << 3);
                    uint32_t a = smem_u32(&sV[r * STRIDE + c]);
                    uint32_t b0, b1, b2, b3;
                    asm volatile("ldmatrix.sync.aligned.m8n8.x4.trans.shared.b16 {%0,%1,%2,%3},[%4];"
                                 : "=r"(b0), "=r"(b1), "=r"(b2), "=r"(b3) : "r"(a));
                    mma16816(oacc[2 * jp],     a0, a1, a2, a3, b0, b1);
                    mma16816(oacc[2 * jp + 1], a0, a1, a2, a3, b2, b3);
                }
            }
        }
    }

    // ---- finalize ----
    l0 += __shfl_xor_sync(0xffffffffu, l0, 1);
    l0 += __shfl_xor_sync(0xffffffffu, l0, 2);
    l1 += __shfl_xor_sync(0xffffffffu, l1, 1);
    l1 += __shfl_xor_sync(0xffffffffu, l1, 2);
    float inv0 = 1.f / fmaxf(l0, 1e-20f);
    float inv1 = 1.f / fmaxf(l1, 1e-20f);

#pragma unroll
    for (int jo = 0; jo < 8; jo++) {
        int c = jo * 8 + tq * 2;
        size_t e0 = base + (size_t)(q0 + warp * 16 + g) * D_ + c;
        size_t e1 = base + (size_t)(q0 + warp * 16 + g + 8) * D_ + c;
        float x0 = oacc[jo][0] * inv0, y0 = oacc[jo][1] * inv0;
        float x1 = oacc[jo][2] * inv1, y1 = oacc[jo][3] * inv1;
        if (mode == 0) {
            float* Of = (float*)O;
            *(float2*)&Of[e0] = make_float2(x0, y0);
            *(float2*)&Of[e1] = make_float2(x1, y1);
        } else if (mode == 1) {
            __half* Oh = (__half*)O;
            *(__half2*)&Oh[e0] = __floats2half2_rn(x0, y0);
            *(__half2*)&Oh[e1] = __floats2half2_rn(x1, y1);
        } else {
            __nv_bfloat16* Ob = (__nv_bfloat16*)O;
            *(__nv_bfloat162*)&Ob[e0] = __floats2bfloat162_rn(x0, y0);
            *(__nv_bfloat162*)&Ob[e1] = __floats2bfloat162_rn(x1, y1);
        }
    }
}

extern "C" void kernel_launch(void* const* d_in, const int* in_sizes, int n_in,
                              void* d_out, int out_size) {
    (void)n_in; (void)out_size;
    const void* Q = d_in[0];
    const void* K = d_in[1];
    const void* V = d_in[2];

    int bh = in_sizes[0] / (S_ * D_);   // B*H = 64
    dim3 grid(S_ / MT, bh);
    swattn_kernel<<<grid, 128>>>(Q, K, V, d_out);
}

// round 9
// speedup vs baseline: 1.9336x; 1.9336x over previous
#include <cuda_runtime.h>
#include <cuda_fp16.h>
#include <cuda_bf16.h>
#include <cstdint>

// Sliding-window block-causal attention. B=4 H=16 S=4096 D=64, BLK=16, W=32.
// R9: pre-pass kernel converts K,V fp32 -> fp16 ONCE into __device__ scratch;
// attention kernel is pure-fp16 FA2 with 2-stage cp.async double buffering
// (no per-tile conversion, no staging round trip).

constexpr int S_ = 4096;
constexpr int D_ = 64;
constexpr int MT = 64;
constexpr int NT = 64;
constexpr int STRIDE = 72;                    // halves (64 + 8 pad)
constexpr int TOT = 4 * 16 * 4096 * 64;       // B*H*S*D = 16777216
constexpr float SL2E = 0.125f * 1.4426950408889634f;

__device__ __half g_K16[TOT];
__device__ __half g_V16[TOT];

__device__ __forceinline__ uint32_t smem_u32(const void* p) {
    return (uint32_t)__cvta_generic_to_shared(p);
}
__device__ __forceinline__ float ex2(float x) {
    float y;
    asm("ex2.approx.ftz.f32 %0, %1;" : "=f"(y) : "f"(x));
    return y;
}
__device__ __forceinline__ void mma16816(float c[4], uint32_t a0, uint32_t a1,
                                         uint32_t a2, uint32_t a3,
                                         uint32_t b0, uint32_t b1) {
    asm volatile(
        "mma.sync.aligned.m16n8k16.row.col.f32.f16.f16.f32 "
        "{%0,%1,%2,%3},{%4,%5,%6,%7},{%8,%9},{%0,%1,%2,%3};"
        : "+f"(c[0]), "+f"(c[1]), "+f"(c[2]), "+f"(c[3])
        : "r"(a0), "r"(a1), "r"(a2), "r"(a3), "r"(b0), "r"(b1));
}
__device__ __forceinline__ void cpasync16(uint32_t dst, const void* src) {
    asm volatile("cp.async.cg.shared.global [%0], [%1], 16;" :: "r"(dst), "l"(src));
}

// dtype probe: classify buffer as fp32(0) / fp16(1) / bf16(2)
__device__ __forceinline__ int probe_mode(const uint32_t* w) {
    int evenCnt = 0, oddCnt = 0;
    for (int i = 0; i < 128; i++) {
        uint32_t x = w[i];
        uint32_t elo = (x >> 7) & 0xff;
        uint32_t ehi = (x >> 23) & 0xff;
        evenCnt += (elo >= 117 && elo <= 132) ? 1 : 0;
        oddCnt  += (ehi >= 117 && ehi <= 132) ? 1 : 0;
    }
    return (oddCnt < 90) ? 1 : ((evenCnt > 102) ? 2 : 0);
}

// ---- pre-pass: convert K,V to fp16 scratch (8 elems/thread) ----
__global__ __launch_bounds__(256)
void cvt_kernel(const void* __restrict__ K, const void* __restrict__ V, int n) {
    __shared__ int s_mode;
    if (threadIdx.x == 0) s_mode = probe_mode((const uint32_t*)K);
    __syncthreads();
    const int mode = s_mode;

    size_t i0 = ((size_t)blockIdx.x * 256 + threadIdx.x) * 8;
    if (i0 + 8 > (size_t)n) return;
    const void* src = blockIdx.y ? V : K;
    __half* dst = blockIdx.y ? g_V16 : g_K16;

    if (mode == 0) {
        const float4* s = (const float4*)((const float*)src + i0);
        float4 a = s[0], b = s[1];
        __half2 h0 = __floats2half2_rn(a.x, a.y);
        __half2 h1 = __floats2half2_rn(a.z, a.w);
        __half2 h2 = __floats2half2_rn(b.x, b.y);
        __half2 h3 = __floats2half2_rn(b.z, b.w);
        *(uint4*)(dst + i0) = make_uint4(*(uint32_t*)&h0, *(uint32_t*)&h1,
                                         *(uint32_t*)&h2, *(uint32_t*)&h3);
    } else if (mode == 1) {
        *(uint4*)(dst + i0) = *(const uint4*)((const uint16_t*)src + i0);
    } else {
        uint4 v = *(const uint4*)((const uint16_t*)src + i0);
        uint32_t* w = (uint32_t*)&v;
#pragma unroll
        for (int e = 0; e < 4; e++) {
            float2 f = __bfloat1622float2(*(__nv_bfloat162*)&w[e]);
            __half2 h = __floats2half2_rn(f.x, f.y);
            w[e] = *(uint32_t*)&h;
        }
        *(uint4*)(dst + i0) = v;
    }
}

// issue one 64x64 fp16 tile via cp.async into padded smem buffer
__device__ __forceinline__ void issue_tile(const __half* gsrc, __half* sdst, int tid) {
#pragma unroll
    for (int i = 0; i < 4; i++) {
        int ch = tid + i * 128;
        int r = ch >> 3, c = ch & 7;
        cpasync16(smem_u32((const char*)sdst + r * 144 + c * 16),
                  (const char*)gsrc + r * 128 + c * 16);
    }
}

__global__ __launch_bounds__(128, 3)
void swattn_kernel(const void* __restrict__ Q, void* __restrict__ O) {
    __shared__ __half sQ[MT * STRIDE];
    __shared__ __half sKV[2][2][NT * STRIDE];   // [stage][K=0/V=1]
    __shared__ int s_mode;

    const int tid  = threadIdx.x;
    const int lane = tid & 31;
    const int warp = tid >> 5;
    const int q0   = blockIdx.x * MT;
    const size_t base = (size_t)blockIdx.y * ((size_t)S_ * D_);

    if (tid == 0) s_mode = probe_mode((const uint32_t*)Q);
    __syncthreads();
    const int mode = s_mode;

    int kt_lo = q0 - 512;
    if (kt_lo < 0) kt_lo = 0;
    const int ntiles = (q0 - kt_lo) / NT + 1;

    // ---- prologue: issue up to 2 tiles ----
    issue_tile(g_K16 + base + (size_t)kt_lo * D_, sKV[0][0], tid);
    issue_tile(g_V16 + base + (size_t)kt_lo * D_, sKV[0][1], tid);
    asm volatile("cp.async.commit_group;");
    if (ntiles > 1) {
        issue_tile(g_K16 + base + (size_t)(kt_lo + NT) * D_, sKV[1][0], tid);
        issue_tile(g_V16 + base + (size_t)(kt_lo + NT) * D_, sKV[1][1], tid);
        asm volatile("cp.async.commit_group;");
    }

    // ---- load Q tile (scaled by SL2E) ----
    if (mode == 0) {
        const float* Qs = (const float*)Q + base + (size_t)q0 * D_;
#pragma unroll
        for (int i = 0; i < 8; i++) {
            int idx = tid + i * 128;
            int r = idx >> 4, c = (idx & 15) * 4;
            float4 v = *(const float4*)&Qs[r * D_ + c];
            *(__half2*)&sQ[r * STRIDE + c]     = __floats2half2_rn(v.x * SL2E, v.y * SL2E);
            *(__half2*)&sQ[r * STRIDE + c + 2] = __floats2half2_rn(v.z * SL2E, v.w * SL2E);
        }
    } else {
        const uint16_t* Qs = (const uint16_t*)Q + base + (size_t)q0 * D_;
#pragma unroll
        for (int i = 0; i < 4; i++) {
            int idx = tid + i * 128;
            int r = idx >> 3, c = (idx & 7) * 8;
            uint4 v = *(const uint4*)&Qs[r * D_ + c];
            uint32_t* w = (uint32_t*)&v;
#pragma unroll
            for (int e = 0; e < 4; e++) {
                float2 f = (mode == 2) ? __bfloat1622float2(*(__nv_bfloat162*)&w[e])
                                       : __half22float2(*(__half2*)&w[e]);
                __half2 h = __floats2half2_rn(f.x * SL2E, f.y * SL2E);
                w[e] = *(uint32_t*)&h;
            }
            *(uint4*)&sQ[r * STRIDE + c] = v;
        }
    }
    __syncthreads();

    // ---- Q fragments ----
    uint32_t qf[4][4];
    {
        int row  = warp * 16 + (lane & 15);
        int colb = (lane >> 4) * 8;
#pragma unroll
        for (int ks = 0; ks < 4; ks++) {
            uint32_t a = smem_u32(&sQ[row * STRIDE + ks * 16 + colb]);
            asm volatile("ldmatrix.sync.aligned.m8n8.x4.shared.b16 {%0,%1,%2,%3},[%4];"
                         : "=r"(qf[ks][0]), "=r"(qf[ks][1]),
                           "=r"(qf[ks][2]), "=r"(qf[ks][3])
                         : "r"(a));
        }
    }

    float oacc[8][4];
#pragma unroll
    for (int j = 0; j < 8; j++) {
        oacc[j][0] = 0.f; oacc[j][1] = 0.f; oacc[j][2] = 0.f; oacc[j][3] = 0.f;
    }
    float l0 = 0.f, l1 = 0.f;

    const int g    = lane >> 2;
    const int tq   = lane & 3;
    const int qr0  = q0 + warp * 16 + g;
    const int qr1  = qr0 + 8;
    const int low0 = (qr0 & ~15) - 496;
    const int low1 = (qr1 & ~15) - 496;

    for (int it = 0; it < ntiles; it++) {
        const int kt = kt_lo + it * NT;
        if (it + 1 < ntiles) {
            asm volatile("cp.async.wait_group 1;");
        } else {
            asm volatile("cp.async.wait_group 0;");
        }
        __syncthreads();

        const __half* sK = sKV[it & 1][0];
        const __half* sV = sKV[it & 1][1];
        const bool full = (kt >= q0 - 448) && (kt + NT <= q0);

        // ---- S = Q @ K^T ----
        float sacc[8][4];
#pragma unroll
        for (int j = 0; j < 8; j++) {
            sacc[j][0] = 0.f; sacc[j][1] = 0.f; sacc[j][2] = 0.f; sacc[j][3] = 0.f;
        }
#pragma unroll
        for (int ks = 0; ks < 4; ks++) {
#pragma unroll
            for (int jp = 0; jp < 4; jp++) {
                int r = jp * 16 + ((lane >> 4) << 3) + (lane & 7);
                int c = ks * 16 + ((lane >> 3) & 1) * 8;
                uint32_t a = smem_u32(&sK[r * STRIDE + c]);
                uint32_t b0, b1, b2, b3;
                asm volatile("ldmatrix.sync.aligned.m8n8.x4.shared.b16 {%0,%1,%2,%3},[%4];"
                             : "=r"(b0), "=r"(b1), "=r"(b2), "=r"(b3) : "r"(a));
                mma16816(sacc[2 * jp],     qf[ks][0], qf[ks][1], qf[ks][2], qf[ks][3], b0, b1);
                mma16816(sacc[2 * jp + 1], qf[ks][0], qf[ks][1], qf[ks][2], qf[ks][3], b2, b3);
            }
        }

        // ---- p = 2^s, masked -> 0 ----
        uint32_t ph[8][2];
        float rs0 = 0.f, rs1 = 0.f;
#pragma unroll
        for (int j = 0; j < 8; j++) {
            float p0 = ex2(sacc[j][0]);
            float p1 = ex2(sacc[j][1]);
            float p2 = ex2(sacc[j][2]);
            float p3 = ex2(sacc[j][3]);
            if (!full) {
                int k0 = kt + j * 8 + tq * 2;
                int k1 = k0 + 1;
                if (!(k0 <= qr0 && k0 >= low0)) p0 = 0.f;
                if (!(k1 <= qr0 && k1 >= low0)) p1 = 0.f;
                if (!(k0 <= qr1 && k0 >= low1)) p2 = 0.f;
                if (!(k1 <= qr1 && k1 >= low1)) p3 = 0.f;
            }
            rs0 += p0 + p1;
            rs1 += p2 + p3;
            __half2 h01 = __floats2half2_rn(p0, p1);
            __half2 h23 = __floats2half2_rn(p2, p3);
            ph[j][0] = *(uint32_t*)&h01;
            ph[j][1] = *(uint32_t*)&h23;
        }
        l0 += rs0;
        l1 += rs1;

        // ---- O += P @ V ----
#pragma unroll
        for (int kk = 0; kk < 4; kk++) {
            uint32_t a0 = ph[2 * kk][0], a1 = ph[2 * kk][1];
            uint32_t a2 = ph[2 * kk + 1][0], a3 = ph[2 * kk + 1][1];
#pragma unroll
            for (int jp = 0; jp < 4; jp++) {
                int r = kk * 16 + (lane & 15);
                int c = jp * 16 + ((lane >> 4) << 3);
                uint32_t a = smem_u32(&sV[r * STRIDE + c]);
                uint32_t b0, b1, b2, b3;
                asm volatile("ldmatrix.sync.aligned.m8n8.x4.trans.shared.b16 {%0,%1,%2,%3},[%4];"
                             : "=r"(b0), "=r"(b1), "=r"(b2), "=r"(b3) : "r"(a));
                mma16816(oacc[2 * jp],     a0, a1, a2, a3, b0, b1);
                mma16816(oacc[2 * jp + 1], a0, a1, a2, a3, b2, b3);
            }
        }
        __syncthreads();   // LDSM reads done before refilling this buffer

        if (it + 2 < ntiles) {
            const size_t off = base + (size_t)(kt + 2 * NT) * D_;
            issue_tile(g_K16 + off, sKV[it & 1][0], tid);
            issue_tile(g_V16 + off, sKV[it & 1][1], tid);
            asm volatile("cp.async.commit_group;");
        }
    }

    // ---- finalize ----
    l0 += __shfl_xor_sync(0xffffffffu, l0, 1);
    l0 += __shfl_xor_sync(0xffffffffu, l0, 2);
    l1 += __shfl_xor_sync(0xffffffffu, l1, 1);
    l1 += __shfl_xor_sync(0xffffffffu, l1, 2);
    float inv0 = 1.f / fmaxf(l0, 1e-20f);
    float inv1 = 1.f / fmaxf(l1, 1e-20f);

#pragma unroll
    for (int jo = 0; jo < 8; jo++) {
        int c = jo * 8 + tq * 2;
        size_t e0 = base + (size_t)(q0 + warp * 16 + g) * D_ + c;
        size_t e1 = base + (size_t)(q0 + warp * 16 + g + 8) * D_ + c;
        float x0 = oacc[jo][0] * inv0, y0 = oacc[jo][1] * inv0;
        float x1 = oacc[jo][2] * inv1, y1 = oacc[jo][3] * inv1;
        if (mode == 0) {
            float* Of = (float*)O;
            *(float2*)&Of[e0] = make_float2(x0, y0);
            *(float2*)&Of[e1] = make_float2(x1, y1);
        } else if (mode == 1) {
            __half* Oh = (__half*)O;
            *(__half2*)&Oh[e0] = __floats2half2_rn(x0, y0);
            *(__half2*)&Oh[e1] = __floats2half2_rn(x1, y1);
        } else {
            __nv_bfloat16* Ob = (__nv_bfloat16*)O;
            *(__nv_bfloat162*)&Ob[e0] = __floats2bfloat162_rn(x0, y0);
            *(__nv_bfloat162*)&Ob[e1] = __floats2bfloat162_rn(x1, y1);
        }
    }
}

extern "C" void kernel_launch(void* const* d_in, const int* in_sizes, int n_in,
                              void* d_out, int out_size) {
    (void)n_in; (void)out_size;
    const void* Q = d_in[0];
    const void* K = d_in[1];
    const void* V = d_in[2];
    int n = in_sizes[0];

    dim3 cgrid((n + 256 * 8 - 1) / (256 * 8), 2);
    cvt_kernel<<<cgrid, 256>>>(K, V, n);

    int bh = n / (S_ * D_);
    dim3 grid(S_ / MT, bh);
    swattn_kernel<<<grid, 128>>>(Q, d_out);
}